// round 13
// baseline (speedup 1.0000x reference)
#include <cuda_runtime.h>
#include <cuda_fp16.h>
#include <math.h>
#include <stdint.h>

// ---------------------------------------------------------------------------
// Problem constants
// ---------------------------------------------------------------------------
#define NB   4
#define LL   4096
#define SEQS 4096
#define CC   512
#define NH   8
#define HD   64
#define C2   1024
#define NTOK (NB * LL)          // 16384
#define EPS_Z 1e-6f
#define LN_EPS 1e-5f

// ---------------------------------------------------------------------------
// Scratch (device globals; no allocation allowed)
// ---------------------------------------------------------------------------
__device__ __align__(16) float g_KV[NB * NH * HD * HD];
__device__ __align__(16) float g_Ks[NB * NH * HD];

// fp16 buffers
__device__ __align__(16) __half g_Qh[(size_t)NTOK * CC];
__device__ __align__(16) __half g_Kh[(size_t)NTOK * CC];
__device__ __align__(16) __half g_Vh[(size_t)NTOK * CC];
__device__ __align__(16) __half g_xh[(size_t)NTOK * CC];
__device__ __align__(16) __half g_yh[(size_t)NTOK * CC];
__device__ __align__(16) __half g_Wqh[CC * CC];
__device__ __align__(16) __half g_Wkh[CC * CC];
__device__ __align__(16) __half g_Wvh[CC * CC];
__device__ __align__(16) __half g_Wmh[CC * CC];
__device__ __align__(16) __half g_W1h[C2 * C2];
__device__ __align__(16) __half g_W2h[CC * C2];
__device__ __align__(16) __half g_Mh  [(size_t)NTOK * CC];
__device__ __align__(16) __half g_M1h [(size_t)NTOK * CC];
__device__ __align__(16) __half g_M2h [(size_t)NTOK * CC];
__device__ __align__(16) __half g_mlnh[(size_t)NTOK * CC];
__device__ __align__(16) __half g_H1h [(size_t)NTOK * C2];

// ---------------------------------------------------------------------------
// PTX helpers
// ---------------------------------------------------------------------------
__device__ __forceinline__ uint32_t smem_u32(const void* p)
{
    uint32_t a;
    asm("{ .reg .u64 t; cvta.to.shared.u64 t, %1; cvt.u32.u64 %0, t; }"
        : "=r"(a) : "l"(p));
    return a;
}

__device__ __forceinline__ void cpasync16(uint32_t dst, const void* src)
{
    asm volatile("cp.async.cg.shared.global [%0], [%1], 16;"
                 :: "r"(dst), "l"(src) : "memory");
}
__device__ __forceinline__ void cp_commit()
{
    asm volatile("cp.async.commit_group;" ::: "memory");
}
template <int N>
__device__ __forceinline__ void cp_wait()
{
    asm volatile("cp.async.wait_group %0;" :: "n"(N) : "memory");
}

__device__ __forceinline__ void ldm_x4(uint32_t& r0, uint32_t& r1,
                                       uint32_t& r2, uint32_t& r3, uint32_t a)
{
    asm volatile("ldmatrix.sync.aligned.m8n8.x4.shared.b16 {%0,%1,%2,%3}, [%4];"
                 : "=r"(r0), "=r"(r1), "=r"(r2), "=r"(r3) : "r"(a));
}

__device__ __forceinline__ void ldm_x4p(uint32_t* r, uint32_t a)
{
    asm volatile("ldmatrix.sync.aligned.m8n8.x4.shared.b16 {%0,%1,%2,%3}, [%4];"
                 : "=r"(r[0]), "=r"(r[1]), "=r"(r[2]), "=r"(r[3]) : "r"(a));
}

__device__ __forceinline__ void ldm_x4_t(uint32_t* r, uint32_t a)
{
    asm volatile("ldmatrix.sync.aligned.m8n8.x4.trans.shared.b16 {%0,%1,%2,%3}, [%4];"
                 : "=r"(r[0]), "=r"(r[1]), "=r"(r[2]), "=r"(r[3]) : "r"(a));
}

__device__ __forceinline__ void mma16816(float* c, const uint32_t* a,
                                         const uint32_t* b)
{
    asm volatile(
        "mma.sync.aligned.m16n8k16.row.col.f32.f16.f16.f32 "
        "{%0,%1,%2,%3}, {%4,%5,%6,%7}, {%8,%9}, {%0,%1,%2,%3};"
        : "+f"(c[0]), "+f"(c[1]), "+f"(c[2]), "+f"(c[3])
        : "r"(a[0]), "r"(a[1]), "r"(a[2]), "r"(a[3]), "r"(b[0]), "r"(b[1]));
}

// ---------------------------------------------------------------------------
// Mega split: fp32 -> fp16
// ---------------------------------------------------------------------------
#define NSPLIT 8
struct SplitJobs {
    const float* src[NSPLIT];
    __half* hi[NSPLIT];
    int n4[NSPLIT];
    int blkoff[NSPLIT + 1];
};

__global__ void __launch_bounds__(256)
split_all(SplitJobs J)
{
    int b = blockIdx.x;
    int j = 0;
#pragma unroll
    for (int t = 0; t < NSPLIT - 1; t++)
        if (b >= J.blkoff[t + 1]) j = t + 1;
    const int i = (b - J.blkoff[j]) * 256 + threadIdx.x;
    if (i >= J.n4[j]) return;
    float4 v = ((const float4*)J.src[j])[i];
    ((__half2*)J.hi[j])[i * 2 + 0] =
        __half2(__float2half_rn(v.x), __float2half_rn(v.y));
    ((__half2*)J.hi[j])[i * 2 + 1] =
        __half2(__float2half_rn(v.z), __float2half_rn(v.w));
}

// ---------------------------------------------------------------------------
// fp16 1-pass HMMA GEMM. Tile 128x128, BK=64 fp32-K, 3-stage cp.async,
// 8 warps 2x4, dual A-source (kSplit in 64-K chunks). EPI:
//   2 = relu -> fp16 Ch
//   4 = merged QKV: seg=bx>>2: 0 -> elu(A1@Bh)->Ch, 1 -> elu(A2@B2h)->Ch2,
//                   2 -> (A2@B3h)*scale -> Ch3
//   5 = *scale -> fp16 Ch
// smem row = 64 halves (128B) + 16B pad = 144B (conflict-free ldmatrix).
// ---------------------------------------------------------------------------
#define ROWB   144
#define MATB   (128 * ROWB)       // 18432 B
#define STAGEB (2 * MATB)         // 36864 B (Ah, Bh)
#define NSTG   3
#define SMEM_GEMM (NSTG * STAGEB) // 110592 B

template <int EPI>
__global__ void __launch_bounds__(256, 2)
hmma_gemm(const __half* __restrict__ A1h, const __half* __restrict__ A2h,
          const __half* __restrict__ Bh, const __half* __restrict__ B2h,
          const __half* __restrict__ B3h,
          __half* __restrict__ Ch, __half* __restrict__ Ch2,
          __half* __restrict__ Ch3,
          int N, int K, int kSplit,
          size_t sA1b, size_t sA2b, float scale)
{
    extern __shared__ __align__(16) uint8_t dynsm[];
    const uint32_t sbase = smem_u32(dynsm);

    const int tid  = threadIdx.x;
    const int wid  = tid >> 5;
    const int lane = tid & 31;
    const int wr   = wid >> 2;
    const int wc   = wid & 3;
    const int bx   = blockIdx.x;
    const int by   = blockIdx.y;

    const int seg = (EPI == 4) ? (bx >> 2) : 0;
    const int bn  = (EPI == 4) ? (bx & 3) : bx;
    const __half* Bsel = Bh;
    if (EPI == 4) Bsel = (seg == 0) ? Bh : ((seg == 1) ? B2h : B3h);
    const int kS = (EPI == 4) ? ((seg == 0) ? 9999 : 0) : kSplit;

    // cp.async geometry: row = tid>>1 (0..127), cb = (tid&1)*64, 4x16B each
    const int rowL = tid >> 1;
    const int cb   = (tid & 1) * 64;
    const size_t sBb = (size_t)K * 2;

    const char* gA1h = (const char*)A1h + (size_t)(by * 128 + rowL) * sA1b + cb;
    const char* gA2h = (const char*)A2h + (size_t)(by * 128 + rowL) * sA2b + cb;
    const char* gBh0 = (const char*)Bsel + (size_t)(bn * 128 + rowL) * sBb + cb;

    const uint32_t dst0 = (uint32_t)(rowL * ROWB + cb);

    auto issue = [&](int stage, int chunk) {
        const uint32_t s = sbase + stage * STAGEB;
        const char *ah; size_t o;
        if (chunk < kS) { ah = gA1h; o = (size_t)chunk * 128; }
        else { ah = gA2h; o = (size_t)(chunk - kS) * 128; }
        const size_t ob = (size_t)chunk * 128;
#pragma unroll
        for (int j = 0; j < 4; j++) {
            cpasync16(s + dst0 + j * 16, ah + o + j * 16);
            cpasync16(s + MATB + dst0 + j * 16, gBh0 + ob + j * 16);
        }
        cp_commit();
    };

    const uint32_t aRow = (uint32_t)(wr * 64 + (lane & 15));
    const uint32_t aCol = (uint32_t)((lane >> 4) << 4);
    const uint32_t bRow = (uint32_t)(wc * 32 + (lane & 7) + ((lane >> 4) << 3));
    const uint32_t bCol = (uint32_t)(((lane >> 3) & 1) << 4);

    float acc[4][4][4];
#pragma unroll
    for (int i = 0; i < 4; i++)
#pragma unroll
        for (int j = 0; j < 4; j++)
#pragma unroll
            for (int q = 0; q < 4; q++) acc[i][j][q] = 0.f;

    const int nch = K / 64;
    issue(0, 0);
    if (nch > 1) issue(1, 1);

    for (int c = 0; c < nch; c++) {
        if (c + 2 < nch) { issue((c + 2) % NSTG, c + 2); cp_wait<2>(); }
        else if (c + 1 < nch) { cp_wait<1>(); }
        else { cp_wait<0>(); }
        __syncthreads();

        const uint32_t s  = sbase + (c % NSTG) * STAGEB;
        const uint32_t pAh = s, pBh = s + MATB;

#pragma unroll
        for (int ks = 0; ks < 4; ks++) {
            const uint32_t kb = (uint32_t)(ks * 32);

            uint32_t ah[4][4], bh[2][4];
#pragma unroll
            for (int mi = 0; mi < 4; mi++)
                ldm_x4(ah[mi][0], ah[mi][1], ah[mi][2], ah[mi][3],
                       pAh + (aRow + mi * 16) * ROWB + kb + aCol);
#pragma unroll
            for (int ng = 0; ng < 2; ng++)
                ldm_x4(bh[ng][0], bh[ng][1], bh[ng][2], bh[ng][3],
                       pBh + (bRow + ng * 16) * ROWB + kb + bCol);
#pragma unroll
            for (int mi = 0; mi < 4; mi++)
#pragma unroll
                for (int ni = 0; ni < 4; ni++)
                    mma16816(acc[mi][ni], ah[mi], &bh[ni >> 1][(ni & 1) * 2]);
        }
        __syncthreads();
    }

    // ---- epilogue
#pragma unroll
    for (int mi = 0; mi < 4; mi++) {
#pragma unroll
        for (int ni = 0; ni < 4; ni++) {
            const int r = by * 128 + wr * 64 + mi * 16 + (lane >> 2);
            const int cn = bn * 128 + wc * 32 + ni * 8 + (lane & 3) * 2;
            float v0 = acc[mi][ni][0];
            float v1 = acc[mi][ni][1];
            float v2 = acc[mi][ni][2];
            float v3 = acc[mi][ni][3];
            if (EPI == 5 || (EPI == 4 && seg == 2)) {
                v0 *= scale; v1 *= scale; v2 *= scale; v3 *= scale;
            }
            if (EPI == 4 && seg < 2) {
                v0 = (v0 > 0.f) ? (v0 + 1.f) : expf(v0);
                v1 = (v1 > 0.f) ? (v1 + 1.f) : expf(v1);
                v2 = (v2 > 0.f) ? (v2 + 1.f) : expf(v2);
                v3 = (v3 > 0.f) ? (v3 + 1.f) : expf(v3);
            }
            if (EPI == 2) {
                v0 = fmaxf(v0, 0.f); v1 = fmaxf(v1, 0.f);
                v2 = fmaxf(v2, 0.f); v3 = fmaxf(v3, 0.f);
            }

            __half* outp = Ch;
            if (EPI == 4) outp = (seg == 0) ? Ch : ((seg == 1) ? Ch2 : Ch3);
            *(__half2*)(outp + (size_t)r * N + cn) =
                __half2(__float2half_rn(v0), __float2half_rn(v1));
            *(__half2*)(outp + (size_t)(r + 8) * N + cn) =
                __half2(__float2half_rn(v2), __float2half_rn(v3));
        }
    }
}

// ---------------------------------------------------------------------------
// Zero KV / Ksum accumulators
// ---------------------------------------------------------------------------
__global__ void zero_kv_kernel()
{
    int i = blockIdx.x * blockDim.x + threadIdx.x;
    if (i < NB * NH * HD * HD) g_KV[i] = 0.f;
    if (i < NB * NH * HD)      g_Ks[i] = 0.f;
}

// ---------------------------------------------------------------------------
// KV via tensor cores: KV[n,h] = K^T @ V (+ Ksum) over this block's s-range.
// ---------------------------------------------------------------------------
#define KV_SPLIT 16
#define KROWB  144
#define KTILEB (64 * KROWB)

__global__ void __launch_bounds__(256)
kv_kernel()
{
    __shared__ __align__(16) uint8_t sm[4 * KTILEB];   // K0,V0,K1,V1
    const uint32_t sbase = smem_u32(sm);

    const int n = blockIdx.z, h = blockIdx.y, sp = blockIdx.x;
    const int s0 = sp * (SEQS / KV_SPLIT);
    const int tid  = threadIdx.x;
    const int wid  = tid >> 5;
    const int lane = tid & 31;
    const int d0   = (wid & 3) * 16;
    const int v0   = (wid >> 2) * 32;

    const char* gK = (const char*)g_Kh + ((size_t)(n * SEQS + s0) * CC + h * HD) * 2;
    const char* gV = (const char*)g_Vh + ((size_t)(n * SEQS + s0) * CC + h * HD) * 2;

    auto issue = [&](int stage, int chunk) {
        const uint32_t sK = sbase + stage * 2 * KTILEB;
        const uint32_t sV = sK + KTILEB;
        const size_t goff = (size_t)chunk * 64 * CC * 2;
#pragma unroll
        for (int i = 0; i < 2; i++) {
            const int slot = tid + i * 256;
            const int r  = slot >> 3;
            const int cc = (slot & 7) * 16;
            cpasync16(sK + r * KROWB + cc, gK + goff + (size_t)r * CC * 2 + cc);
            cpasync16(sV + r * KROWB + cc, gV + goff + (size_t)r * CC * 2 + cc);
        }
        cp_commit();
    };

    const uint32_t aRow = (uint32_t)(((lane >> 4) << 3) + (lane & 7));
    const uint32_t aCol = (uint32_t)((d0 + ((lane >> 3) & 1) * 8) * 2);
    const uint32_t bRow = (uint32_t)((((lane >> 3) & 1) << 3) + (lane & 7));
    const uint32_t bColBase = (uint32_t)((v0 + (lane >> 4) * 8) * 2);

    float acc[4][4];
#pragma unroll
    for (int i = 0; i < 4; i++)
#pragma unroll
        for (int q = 0; q < 4; q++) acc[i][q] = 0.f;
    float ksacc = 0.f;

    issue(0, 0);
    const int nch = (SEQS / KV_SPLIT) / 64;

    for (int c = 0; c < nch; c++) {
        cp_wait<0>();
        __syncthreads();
        if (c + 1 < nch) issue((c + 1) & 1, c + 1);

        const uint32_t sK = sbase + (c & 1) * 2 * KTILEB;
        const uint32_t sV = sK + KTILEB;

#pragma unroll
        for (int ks = 0; ks < 4; ks++) {
            const uint32_t srow = (uint32_t)(ks * 16);
            uint32_t a[4], b0[4], b1[4];
            ldm_x4_t(a,  sK + (srow + aRow) * KROWB + aCol);
            ldm_x4_t(b0, sV + (srow + bRow) * KROWB + bColBase);
            ldm_x4_t(b1, sV + (srow + bRow) * KROWB + bColBase + 32);
            mma16816(acc[0], a, &b0[0]);
            mma16816(acc[1], a, &b0[2]);
            mma16816(acc[2], a, &b1[0]);
            mma16816(acc[3], a, &b1[2]);
        }

        if (tid < HD) {
            const uint32_t boff = (c & 1) * 2 * KTILEB + (uint32_t)(tid * 2);
#pragma unroll 8
            for (int s = 0; s < 64; s++)
                ksacc += __half2float(*(const __half*)(sm + boff + s * KROWB));
        }
        __syncthreads();
    }

    float* KVp = g_KV + (size_t)(n * NH + h) * HD * HD;
    const int dr = d0 + (lane >> 2);
    const int vc = (lane & 3) * 2;
#pragma unroll
    for (int ni = 0; ni < 4; ni++) {
        const int v = v0 + ni * 8 + vc;
        atomicAdd(&KVp[(size_t)dr * HD + v],           acc[ni][0]);
        atomicAdd(&KVp[(size_t)dr * HD + v + 1],       acc[ni][1]);
        atomicAdd(&KVp[(size_t)(dr + 8) * HD + v],     acc[ni][2]);
        atomicAdd(&KVp[(size_t)(dr + 8) * HD + v + 1], acc[ni][3]);
    }
    if (tid < HD)
        atomicAdd(&g_Ks[(n * NH + h) * HD + tid], ksacc);
}

// ---------------------------------------------------------------------------
// msg via tensor cores: per (n,h,128-l-tile):
//   M[l, h*64+v] = S * (Q[l,:] @ KV[:,v]) / (Q[l,:] . Ksum + eps)
// ---------------------------------------------------------------------------
#define MROWB 144
__global__ void __launch_bounds__(128)
msg_tc_kernel()
{
    __shared__ __align__(16) uint8_t smQ[128 * MROWB];
    __shared__ __align__(16) uint8_t smB[64 * MROWB];   // KV fp16, rows=d cols=v
    __shared__ float Kss[HD];

    const int n = blockIdx.z, h = blockIdx.y, lt = blockIdx.x;
    const int tid  = threadIdx.x;
    const int wr   = tid >> 5;
    const int lane = tid & 31;

    const uint32_t sQ = smem_u32(smQ);
    const uint32_t sB = smem_u32(smB);

    const char* gQ = (const char*)g_Qh +
        ((size_t)(n * LL + lt * 128) * CC + h * HD) * 2;
    const float* gKV = g_KV + (size_t)(n * NH + h) * HD * HD;

#pragma unroll
    for (int i = 0; i < 8; i++) {
        const int slot = tid + i * 128;
        const int r = slot >> 3, c = (slot & 7) * 16;
        cpasync16(sQ + r * MROWB + c, gQ + (size_t)r * CC * 2 + c);
    }
    cp_commit();

#pragma unroll
    for (int i = 0; i < 32; i++) {
        const int idx = tid + i * 128;
        const int d = idx >> 6, v = idx & 63;
        *(__half*)(smB + d * MROWB + v * 2) = __float2half_rn(gKV[idx]);
    }
    if (tid < HD) Kss[tid] = g_Ks[(n * NH + h) * HD + tid];
    cp_wait<0>();
    __syncthreads();

    const uint32_t aRow = (uint32_t)(wr * 32 + (lane & 15));
    const uint32_t aCol = (uint32_t)((lane >> 4) << 4);
    const uint32_t bRow = (uint32_t)((((lane >> 3) & 1) << 3) + (lane & 7));
    const uint32_t bColB = (uint32_t)((lane >> 4) << 4);

    float acc[2][8][4];
#pragma unroll
    for (int i = 0; i < 2; i++)
#pragma unroll
        for (int j = 0; j < 8; j++)
#pragma unroll
            for (int q = 0; q < 4; q++) acc[i][j][q] = 0.f;

#pragma unroll
    for (int ks = 0; ks < 4; ks++) {
        const uint32_t kb = (uint32_t)(ks * 32);
        uint32_t a[2][4], b[4][4];
#pragma unroll
        for (int mi = 0; mi < 2; mi++)
            ldm_x4p(a[mi], sQ + (aRow + mi * 16) * MROWB + kb + aCol);
#pragma unroll
        for (int g = 0; g < 4; g++)
            ldm_x4_t(b[g], sB + (ks * 16 + bRow) * MROWB + bColB + g * 32);
#pragma unroll
        for (int mi = 0; mi < 2; mi++)
#pragma unroll
            for (int ni = 0; ni < 8; ni++)
                mma16816(acc[mi][ni], a[mi], &b[ni >> 1][(ni & 1) * 2]);
    }

#pragma unroll
    for (int mi = 0; mi < 2; mi++) {
        const int r0 = wr * 32 + mi * 16 + (lane >> 2);
        float zd0 = EPS_Z, zd1 = EPS_Z;
        const __half2* q0 = (const __half2*)(smQ + r0 * MROWB);
        const __half2* q1 = (const __half2*)(smQ + (r0 + 8) * MROWB);
#pragma unroll
        for (int k = 0; k < HD / 2; k++) {
            const float2 a0 = __half22float2(q0[k]);
            const float2 a1 = __half22float2(q1[k]);
            zd0 = fmaf(a0.x, Kss[2 * k], fmaf(a0.y, Kss[2 * k + 1], zd0));
            zd1 = fmaf(a1.x, Kss[2 * k], fmaf(a1.y, Kss[2 * k + 1], zd1));
        }
        const float zs0 = (float)SEQS / zd0;
        const float zs1 = (float)SEQS / zd1;

        const size_t base0 = ((size_t)(n * LL + lt * 128 + r0)) * CC + h * HD;
        const size_t base1 = base0 + (size_t)8 * CC;
#pragma unroll
        for (int ni = 0; ni < 8; ni++) {
            const int cn = ni * 8 + (lane & 3) * 2;
            *(__half2*)(g_Mh + base0 + cn) =
                __half2(__float2half_rn(acc[mi][ni][0] * zs0),
                        __float2half_rn(acc[mi][ni][1] * zs0));
            *(__half2*)(g_Mh + base1 + cn) =
                __half2(__float2half_rn(acc[mi][ni][2] * zs1),
                        __float2half_rn(acc[mi][ni][3] * zs1));
        }
    }
}

// ---------------------------------------------------------------------------
// Block reduction helper (256 threads)
// ---------------------------------------------------------------------------
__device__ __forceinline__ float block_reduce_sum(float v)
{
    __shared__ float red[8];
    const int lane = threadIdx.x & 31, w = threadIdx.x >> 5;
#pragma unroll
    for (int o = 16; o; o >>= 1) v += __shfl_down_sync(0xffffffffu, v, o);
    if (lane == 0) red[w] = v;
    __syncthreads();
    float t = (threadIdx.x < 8) ? red[threadIdx.x] : 0.f;
    if (w == 0) {
#pragma unroll
        for (int o = 4; o; o >>= 1) t += __shfl_down_sync(0xffu, t, o);
        if (lane == 0) red[0] = t;
    }
    __syncthreads();
    float r = red[0];
    __syncthreads();
    return r;
}

// ---------------------------------------------------------------------------
// LN(M1 fp16) -> fp16. Fully vectorized: 256 threads x one half2 (CC=512).
// ---------------------------------------------------------------------------
__global__ void __launch_bounds__(256)
ln_split_kernel(const float* __restrict__ g, const float* __restrict__ b)
{
    const int row = blockIdx.x;
    const int tid = threadIdx.x;

    const float2 mv = __half22float2(
        *(const __half2*)(g_M1h + (size_t)row * CC + tid * 2));

    const float mean = block_reduce_sum(mv.x + mv.y) * (1.f / CC);
    const float d0 = mv.x - mean, d1 = mv.y - mean;
    const float var = block_reduce_sum(d0 * d0 + d1 * d1) * (1.f / CC);
    const float rstd = rsqrtf(var + LN_EPS);

    const float2 gv = *(const float2*)(g + tid * 2);
    const float2 bv = *(const float2*)(b + tid * 2);
    *(__half2*)(g_mlnh + (size_t)row * CC + tid * 2) =
        __half2(__float2half_rn(d0 * rstd * gv.x + bv.x),
                __float2half_rn(d1 * rstd * gv.y + bv.y));
}

// ---------------------------------------------------------------------------
// out = x + LN(M2 fp16). Fully vectorized: 256 threads x one half2/float2.
// ---------------------------------------------------------------------------
__global__ void __launch_bounds__(256)
ln_add_kernel(const float* __restrict__ x,
              const float* __restrict__ g, const float* __restrict__ b,
              float* __restrict__ out)
{
    const int row = blockIdx.x;
    const int tid = threadIdx.x;

    const float2 mv = __half22float2(
        *(const __half2*)(g_M2h + (size_t)row * CC + tid * 2));

    const float mean = block_reduce_sum(mv.x + mv.y) * (1.f / CC);
    const float d0 = mv.x - mean, d1 = mv.y - mean;
    const float var = block_reduce_sum(d0 * d0 + d1 * d1) * (1.f / CC);
    const float rstd = rsqrtf(var + LN_EPS);

    const float2 gv = *(const float2*)(g + tid * 2);
    const float2 bv = *(const float2*)(b + tid * 2);
    const float2 xv = *(const float2*)(x + (size_t)row * CC + tid * 2);
    *(float2*)(out + (size_t)row * CC + tid * 2) =
        make_float2(xv.x + d0 * rstd * gv.x + bv.x,
                    xv.y + d1 * rstd * gv.y + bv.y);
}

// ---------------------------------------------------------------------------
// Launcher
// ---------------------------------------------------------------------------
extern "C" void kernel_launch(void* const* d_in, const int* in_sizes, int n_in,
                              void* d_out, int out_size)
{
    const float* x  = (const float*)d_in[0];
    const float* y  = (const float*)d_in[1];
    const float* Wq = (const float*)d_in[2];
    const float* Wk = (const float*)d_in[3];
    const float* Wv = (const float*)d_in[4];
    const float* Wm = (const float*)d_in[5];
    const float* W1 = (const float*)d_in[6];
    const float* W2 = (const float*)d_in[7];
    const float* g1 = (const float*)d_in[8];
    const float* b1 = (const float*)d_in[9];
    const float* g2 = (const float*)d_in[10];
    const float* b2 = (const float*)d_in[11];
    float* out = (float*)d_out;

    __half *qh,*kh,*vh,*xh,*yh,*wqh,*wkh,*wvh,*wmh,*w1h,*w2h;
    __half *mh,*m1h,*m2h,*mlnh,*h1h;
    cudaGetSymbolAddress((void**)&qh,  g_Qh);
    cudaGetSymbolAddress((void**)&kh,  g_Kh);
    cudaGetSymbolAddress((void**)&vh,  g_Vh);
    cudaGetSymbolAddress((void**)&xh,  g_xh);
    cudaGetSymbolAddress((void**)&yh,  g_yh);
    cudaGetSymbolAddress((void**)&wqh, g_Wqh);
    cudaGetSymbolAddress((void**)&wkh, g_Wkh);
    cudaGetSymbolAddress((void**)&wvh, g_Wvh);
    cudaGetSymbolAddress((void**)&wmh, g_Wmh);
    cudaGetSymbolAddress((void**)&w1h, g_W1h);
    cudaGetSymbolAddress((void**)&w2h, g_W2h);
    cudaGetSymbolAddress((void**)&mh,  g_Mh);
    cudaGetSymbolAddress((void**)&m1h, g_M1h);
    cudaGetSymbolAddress((void**)&m2h, g_M2h);
    cudaGetSymbolAddress((void**)&mlnh,g_mlnh);
    cudaGetSymbolAddress((void**)&h1h, g_H1h);

    cudaFuncSetAttribute(hmma_gemm<2>, cudaFuncAttributeMaxDynamicSharedMemorySize, SMEM_GEMM);
    cudaFuncSetAttribute(hmma_gemm<4>, cudaFuncAttributeMaxDynamicSharedMemorySize, SMEM_GEMM);
    cudaFuncSetAttribute(hmma_gemm<5>, cudaFuncAttributeMaxDynamicSharedMemorySize, SMEM_GEMM);

    // ---- one mega split launch
    SplitJobs J;
    const float* srcs[NSPLIT] = {x, y, Wq, Wk, Wv, Wm, W1, W2};
    __half* his[NSPLIT] = {xh, yh, wqh, wkh, wvh, wmh, w1h, w2h};
    const int n4s[NSPLIT] = {NTOK * CC / 4, NTOK * CC / 4, CC * CC / 4, CC * CC / 4,
                             CC * CC / 4, CC * CC / 4, C2 * C2 / 4, CC * C2 / 4};
    int off = 0;
    for (int j = 0; j < NSPLIT; j++) {
        J.src[j] = srcs[j]; J.hi[j] = his[j]; J.n4[j] = n4s[j];
        J.blkoff[j] = off;
        off += (n4s[j] + 255) / 256;
    }
    J.blkoff[NSPLIT] = off;
    split_all<<<off, 256>>>(J);

    const dim3 gQKV(3 * CC / 128, NTOK / 128);  // 12 x 128 (Q, K, V)
    const dim3 gP  (CC / 128, NTOK / 128);      // 4 x 128
    const dim3 gW1 (C2 / 128, NTOK / 128);      // 8 x 128
    const size_t sC = (size_t)CC * 2, sC2 = (size_t)C2 * 2;

    // merged Q,K,V projections
    hmma_gemm<4><<<gQKV, 256, SMEM_GEMM>>>(xh, yh, wqh, wkh, wvh,
                                           qh, kh, vh, CC, CC, 9999,
                                           sC, sC, 1.f / (float)SEQS);

    zero_kv_kernel<<<(NB * NH * HD * HD + 255) / 256, 256>>>();
    kv_kernel<<<dim3(KV_SPLIT, NH, NB), 256>>>();
    msg_tc_kernel<<<dim3(LL / 128, NH, NB), 128>>>();

    // Wm: fp16 message -> fp16 M1
    hmma_gemm<5><<<gP, 256, SMEM_GEMM>>>(mh, mh, wmh, nullptr, nullptr,
                                         m1h, nullptr, nullptr,
                                         CC, CC, 9999, sC, sC, 1.f);
    ln_split_kernel<<<NTOK, 256>>>(g1, b1);
    // W1: relu -> fp16; A = [x | LN(msg)] dual source (chunks 0-7 x, 8-15 mln)
    hmma_gemm<2><<<gW1, 256, SMEM_GEMM>>>(xh, mlnh, w1h, nullptr, nullptr,
                                          h1h, nullptr, nullptr,
                                          C2, C2, 8, sC, sC, 1.f);
    // W2 -> fp16 M2
    hmma_gemm<5><<<gP, 256, SMEM_GEMM>>>(h1h, h1h, w2h, nullptr, nullptr,
                                         m2h, nullptr, nullptr,
                                         CC, C2, 9999, sC2, sC2, 1.f);
    ln_add_kernel<<<NTOK, 256>>>(x, g2, b2, out);
}

// round 14
// speedup vs baseline: 1.1813x; 1.1813x over previous
#include <cuda_runtime.h>
#include <cuda_fp16.h>
#include <math.h>
#include <stdint.h>

// ---------------------------------------------------------------------------
// Problem constants
// ---------------------------------------------------------------------------
#define NB   4
#define LL   4096
#define SEQS 4096
#define CC   512
#define NH   8
#define HD   64
#define C2   1024
#define NTOK (NB * LL)          // 16384
#define EPS_Z 1e-6f
#define LN_EPS 1e-5f

// ---------------------------------------------------------------------------
// Scratch (device globals; no allocation allowed)
// ---------------------------------------------------------------------------
__device__ __align__(16) float g_KV[NB * NH * HD * HD];
__device__ __align__(16) float g_Ks[NB * NH * HD];

// fp16 buffers
__device__ __align__(16) __half g_Qh[(size_t)NTOK * CC];
__device__ __align__(16) __half g_Kh[(size_t)NTOK * CC];
__device__ __align__(16) __half g_Vh[(size_t)NTOK * CC];
__device__ __align__(16) __half g_xh[(size_t)NTOK * CC];
__device__ __align__(16) __half g_yh[(size_t)NTOK * CC];
__device__ __align__(16) __half g_Wqh[CC * CC];
__device__ __align__(16) __half g_Wkh[CC * CC];
__device__ __align__(16) __half g_Wvh[CC * CC];
__device__ __align__(16) __half g_Wmh[CC * CC];
__device__ __align__(16) __half g_W1h[C2 * C2];
__device__ __align__(16) __half g_W2h[CC * C2];
__device__ __align__(16) __half g_Mh  [(size_t)NTOK * CC];
__device__ __align__(16) __half g_M1h [(size_t)NTOK * CC];
__device__ __align__(16) __half g_M2h [(size_t)NTOK * CC];
__device__ __align__(16) __half g_mlnh[(size_t)NTOK * CC];
__device__ __align__(16) __half g_H1h [(size_t)NTOK * C2];

// ---------------------------------------------------------------------------
// PTX helpers
// ---------------------------------------------------------------------------
__device__ __forceinline__ uint32_t smem_u32(const void* p)
{
    uint32_t a;
    asm("{ .reg .u64 t; cvta.to.shared.u64 t, %1; cvt.u32.u64 %0, t; }"
        : "=r"(a) : "l"(p));
    return a;
}

__device__ __forceinline__ void cpasync16(uint32_t dst, const void* src)
{
    asm volatile("cp.async.cg.shared.global [%0], [%1], 16;"
                 :: "r"(dst), "l"(src) : "memory");
}
__device__ __forceinline__ void cp_commit()
{
    asm volatile("cp.async.commit_group;" ::: "memory");
}
template <int N>
__device__ __forceinline__ void cp_wait()
{
    asm volatile("cp.async.wait_group %0;" :: "n"(N) : "memory");
}

__device__ __forceinline__ void ldm_x4(uint32_t& r0, uint32_t& r1,
                                       uint32_t& r2, uint32_t& r3, uint32_t a)
{
    asm volatile("ldmatrix.sync.aligned.m8n8.x4.shared.b16 {%0,%1,%2,%3}, [%4];"
                 : "=r"(r0), "=r"(r1), "=r"(r2), "=r"(r3) : "r"(a));
}

__device__ __forceinline__ void ldm_x4p(uint32_t* r, uint32_t a)
{
    asm volatile("ldmatrix.sync.aligned.m8n8.x4.shared.b16 {%0,%1,%2,%3}, [%4];"
                 : "=r"(r[0]), "=r"(r[1]), "=r"(r[2]), "=r"(r[3]) : "r"(a));
}

__device__ __forceinline__ void ldm_x4_t(uint32_t* r, uint32_t a)
{
    asm volatile("ldmatrix.sync.aligned.m8n8.x4.trans.shared.b16 {%0,%1,%2,%3}, [%4];"
                 : "=r"(r[0]), "=r"(r[1]), "=r"(r[2]), "=r"(r[3]) : "r"(a));
}

__device__ __forceinline__ void mma16816(float* c, const uint32_t* a,
                                         const uint32_t* b)
{
    asm volatile(
        "mma.sync.aligned.m16n8k16.row.col.f32.f16.f16.f32 "
        "{%0,%1,%2,%3}, {%4,%5,%6,%7}, {%8,%9}, {%0,%1,%2,%3};"
        : "+f"(c[0]), "+f"(c[1]), "+f"(c[2]), "+f"(c[3])
        : "r"(a[0]), "r"(a[1]), "r"(a[2]), "r"(a[3]), "r"(b[0]), "r"(b[1]));
}

// ---------------------------------------------------------------------------
// Mega split: fp32 -> fp16
// ---------------------------------------------------------------------------
#define NSPLIT 8
struct SplitJobs {
    const float* src[NSPLIT];
    __half* hi[NSPLIT];
    int n4[NSPLIT];
    int blkoff[NSPLIT + 1];
};

__global__ void __launch_bounds__(256)
split_all(SplitJobs J)
{
    int b = blockIdx.x;
    int j = 0;
#pragma unroll
    for (int t = 0; t < NSPLIT - 1; t++)
        if (b >= J.blkoff[t + 1]) j = t + 1;
    const int i = (b - J.blkoff[j]) * 256 + threadIdx.x;
    if (i >= J.n4[j]) return;
    float4 v = ((const float4*)J.src[j])[i];
    ((__half2*)J.hi[j])[i * 2 + 0] =
        __half2(__float2half_rn(v.x), __float2half_rn(v.y));
    ((__half2*)J.hi[j])[i * 2 + 1] =
        __half2(__float2half_rn(v.z), __float2half_rn(v.w));
}

// ---------------------------------------------------------------------------
// fp16 1-pass HMMA GEMM. Tile 128x128, BK=32 fp32-K, 4-stage cp.async,
// 8 warps 2x4, dual A-source (kSplit). EPI:
//   2 = relu -> fp16 Ch
//   4 = merged QKV: seg=bx>>2: 0 -> elu(A1@Bh)->Ch, 1 -> elu(A2@B2h)->Ch2,
//                   2 -> (A2@B3h)*scale -> Ch3
//   5 = *scale -> fp16 Ch
// ---------------------------------------------------------------------------
#define ROWB   80
#define MATB   (128 * ROWB)       // 10240 B
#define STAGEB (2 * MATB)         // 20480 B (Ah, Bh)
#define NSTG   4
#define SMEM_GEMM (NSTG * STAGEB) // 81920 B

template <int EPI>
__global__ void __launch_bounds__(256, 2)
hmma_gemm(const __half* __restrict__ A1h, const __half* __restrict__ A2h,
          const __half* __restrict__ Bh, const __half* __restrict__ B2h,
          const __half* __restrict__ B3h,
          __half* __restrict__ Ch, __half* __restrict__ Ch2,
          __half* __restrict__ Ch3,
          int N, int K, int kSplit,
          size_t sA1b, size_t sA2b, float scale)
{
    extern __shared__ __align__(16) uint8_t dynsm[];
    const uint32_t sbase = smem_u32(dynsm);

    const int tid  = threadIdx.x;
    const int wid  = tid >> 5;
    const int lane = tid & 31;
    const int wr   = wid >> 2;
    const int wc   = wid & 3;
    const int bx   = blockIdx.x;
    const int by   = blockIdx.y;

    const int seg = (EPI == 4) ? (bx >> 2) : 0;
    const int bn  = (EPI == 4) ? (bx & 3) : bx;
    const __half* Bsel = Bh;
    if (EPI == 4) Bsel = (seg == 0) ? Bh : ((seg == 1) ? B2h : B3h);
    const int kS = (EPI == 4) ? ((seg == 0) ? 9999 : 0) : kSplit;

    const int row0 = tid >> 2;               // 0..63
    const int cb   = (tid & 3) * 16;
    const size_t sBb = (size_t)K * 2;

    const char* gA1h = (const char*)A1h + (size_t)(by * 128 + row0) * sA1b + cb;
    const char* gA2h = (const char*)A2h + (size_t)(by * 128 + row0) * sA2b + cb;
    const char* gBh0 = (const char*)Bsel + (size_t)(bn * 128 + row0) * sBb + cb;
    const size_t rs1 = 64 * sA1b, rs2 = 64 * sA2b, rsB = 64 * sBb;

    const uint32_t dA0 = (uint32_t)(row0 * ROWB + cb);
    const uint32_t dA1 = (uint32_t)((row0 + 64) * ROWB + cb);

    auto issue = [&](int stage, int chunk) {
        const uint32_t s = sbase + stage * STAGEB;
        const char *ah; size_t o, rs;
        if (chunk < kS) { ah = gA1h; o = (size_t)chunk * 64; rs = rs1; }
        else { ah = gA2h; o = (size_t)(chunk - kS) * 64; rs = rs2; }
        cpasync16(s + dA0, ah + o);
        cpasync16(s + dA1, ah + o + rs);
        const size_t ob = (size_t)chunk * 64;
        cpasync16(s + MATB + dA0, gBh0 + ob);
        cpasync16(s + MATB + dA1, gBh0 + ob + rsB);
        cp_commit();
    };

    const uint32_t aRow = (uint32_t)(wr * 64 + (lane & 15));
    const uint32_t aCol = (uint32_t)((lane >> 4) << 4);
    const uint32_t bRow = (uint32_t)(wc * 32 + (lane & 7) + ((lane >> 4) << 3));
    const uint32_t bCol = (uint32_t)(((lane >> 3) & 1) << 4);

    float acc[4][4][4];
#pragma unroll
    for (int i = 0; i < 4; i++)
#pragma unroll
        for (int j = 0; j < 4; j++)
#pragma unroll
            for (int q = 0; q < 4; q++) acc[i][j][q] = 0.f;

    const int nch = K / 32;
    issue(0, 0);
    if (nch > 1) issue(1, 1);

    for (int c = 0; c < nch; c++) {
        if (c + 2 < nch) { issue((c + 2) % NSTG, c + 2); cp_wait<2>(); }
        else if (c + 1 < nch) { cp_wait<1>(); }
        else { cp_wait<0>(); }
        __syncthreads();

        const uint32_t s  = sbase + (c % NSTG) * STAGEB;
        const uint32_t pAh = s, pBh = s + MATB;

#pragma unroll
        for (int ks = 0; ks < 2; ks++) {
            const uint32_t kb = (uint32_t)(ks * 32);

            uint32_t ah[4][4], bh[2][4];
#pragma unroll
            for (int mi = 0; mi < 4; mi++)
                ldm_x4(ah[mi][0], ah[mi][1], ah[mi][2], ah[mi][3],
                       pAh + (aRow + mi * 16) * ROWB + kb + aCol);
#pragma unroll
            for (int ng = 0; ng < 2; ng++)
                ldm_x4(bh[ng][0], bh[ng][1], bh[ng][2], bh[ng][3],
                       pBh + (bRow + ng * 16) * ROWB + kb + bCol);
#pragma unroll
            for (int mi = 0; mi < 4; mi++)
#pragma unroll
                for (int ni = 0; ni < 4; ni++)
                    mma16816(acc[mi][ni], ah[mi], &bh[ni >> 1][(ni & 1) * 2]);
        }
        __syncthreads();
    }

    // ---- epilogue
#pragma unroll
    for (int mi = 0; mi < 4; mi++) {
#pragma unroll
        for (int ni = 0; ni < 4; ni++) {
            const int r = by * 128 + wr * 64 + mi * 16 + (lane >> 2);
            const int cn = bn * 128 + wc * 32 + ni * 8 + (lane & 3) * 2;
            float v0 = acc[mi][ni][0];
            float v1 = acc[mi][ni][1];
            float v2 = acc[mi][ni][2];
            float v3 = acc[mi][ni][3];
            if (EPI == 5 || (EPI == 4 && seg == 2)) {
                v0 *= scale; v1 *= scale; v2 *= scale; v3 *= scale;
            }
            if (EPI == 4 && seg < 2) {
                v0 = (v0 > 0.f) ? (v0 + 1.f) : expf(v0);
                v1 = (v1 > 0.f) ? (v1 + 1.f) : expf(v1);
                v2 = (v2 > 0.f) ? (v2 + 1.f) : expf(v2);
                v3 = (v3 > 0.f) ? (v3 + 1.f) : expf(v3);
            }
            if (EPI == 2) {
                v0 = fmaxf(v0, 0.f); v1 = fmaxf(v1, 0.f);
                v2 = fmaxf(v2, 0.f); v3 = fmaxf(v3, 0.f);
            }

            __half* outp = Ch;
            if (EPI == 4) outp = (seg == 0) ? Ch : ((seg == 1) ? Ch2 : Ch3);
            *(__half2*)(outp + (size_t)r * N + cn) =
                __half2(__float2half_rn(v0), __float2half_rn(v1));
            *(__half2*)(outp + (size_t)(r + 8) * N + cn) =
                __half2(__float2half_rn(v2), __float2half_rn(v3));
        }
    }
}

// ---------------------------------------------------------------------------
// Zero KV / Ksum accumulators
// ---------------------------------------------------------------------------
__global__ void zero_kv_kernel()
{
    int i = blockIdx.x * blockDim.x + threadIdx.x;
    if (i < NB * NH * HD * HD) g_KV[i] = 0.f;
    if (i < NB * NH * HD)      g_Ks[i] = 0.f;
}

// ---------------------------------------------------------------------------
// KV via tensor cores: KV[n,h] = K^T @ V (+ Ksum) over this block's s-range.
// ---------------------------------------------------------------------------
#define KV_SPLIT 16
#define KROWB  144
#define KTILEB (64 * KROWB)

__global__ void __launch_bounds__(256)
kv_kernel()
{
    __shared__ __align__(16) uint8_t sm[4 * KTILEB];   // K0,V0,K1,V1
    const uint32_t sbase = smem_u32(sm);

    const int n = blockIdx.z, h = blockIdx.y, sp = blockIdx.x;
    const int s0 = sp * (SEQS / KV_SPLIT);
    const int tid  = threadIdx.x;
    const int wid  = tid >> 5;
    const int lane = tid & 31;
    const int d0   = (wid & 3) * 16;
    const int v0   = (wid >> 2) * 32;

    const char* gK = (const char*)g_Kh + ((size_t)(n * SEQS + s0) * CC + h * HD) * 2;
    const char* gV = (const char*)g_Vh + ((size_t)(n * SEQS + s0) * CC + h * HD) * 2;

    auto issue = [&](int stage, int chunk) {
        const uint32_t sK = sbase + stage * 2 * KTILEB;
        const uint32_t sV = sK + KTILEB;
        const size_t goff = (size_t)chunk * 64 * CC * 2;
#pragma unroll
        for (int i = 0; i < 2; i++) {
            const int slot = tid + i * 256;
            const int r  = slot >> 3;
            const int cc = (slot & 7) * 16;
            cpasync16(sK + r * KROWB + cc, gK + goff + (size_t)r * CC * 2 + cc);
            cpasync16(sV + r * KROWB + cc, gV + goff + (size_t)r * CC * 2 + cc);
        }
        cp_commit();
    };

    const uint32_t aRow = (uint32_t)(((lane >> 4) << 3) + (lane & 7));
    const uint32_t aCol = (uint32_t)((d0 + ((lane >> 3) & 1) * 8) * 2);
    const uint32_t bRow = (uint32_t)((((lane >> 3) & 1) << 3) + (lane & 7));
    const uint32_t bColBase = (uint32_t)((v0 + (lane >> 4) * 8) * 2);

    float acc[4][4];
#pragma unroll
    for (int i = 0; i < 4; i++)
#pragma unroll
        for (int q = 0; q < 4; q++) acc[i][q] = 0.f;
    float ksacc = 0.f;

    issue(0, 0);
    const int nch = (SEQS / KV_SPLIT) / 64;

    for (int c = 0; c < nch; c++) {
        cp_wait<0>();
        __syncthreads();
        if (c + 1 < nch) issue((c + 1) & 1, c + 1);

        const uint32_t sK = sbase + (c & 1) * 2 * KTILEB;
        const uint32_t sV = sK + KTILEB;

#pragma unroll
        for (int ks = 0; ks < 4; ks++) {
            const uint32_t srow = (uint32_t)(ks * 16);
            uint32_t a[4], b0[4], b1[4];
            ldm_x4_t(a,  sK + (srow + aRow) * KROWB + aCol);
            ldm_x4_t(b0, sV + (srow + bRow) * KROWB + bColBase);
            ldm_x4_t(b1, sV + (srow + bRow) * KROWB + bColBase + 32);
            mma16816(acc[0], a, &b0[0]);
            mma16816(acc[1], a, &b0[2]);
            mma16816(acc[2], a, &b1[0]);
            mma16816(acc[3], a, &b1[2]);
        }

        if (tid < HD) {
            const uint32_t boff = (c & 1) * 2 * KTILEB + (uint32_t)(tid * 2);
#pragma unroll 8
            for (int s = 0; s < 64; s++)
                ksacc += __half2float(*(const __half*)(sm + boff + s * KROWB));
        }
        __syncthreads();
    }

    float* KVp = g_KV + (size_t)(n * NH + h) * HD * HD;
    const int dr = d0 + (lane >> 2);
    const int vc = (lane & 3) * 2;
#pragma unroll
    for (int ni = 0; ni < 4; ni++) {
        const int v = v0 + ni * 8 + vc;
        atomicAdd(&KVp[(size_t)dr * HD + v],           acc[ni][0]);
        atomicAdd(&KVp[(size_t)dr * HD + v + 1],       acc[ni][1]);
        atomicAdd(&KVp[(size_t)(dr + 8) * HD + v],     acc[ni][2]);
        atomicAdd(&KVp[(size_t)(dr + 8) * HD + v + 1], acc[ni][3]);
    }
    if (tid < HD)
        atomicAdd(&g_Ks[(n * NH + h) * HD + tid], ksacc);
}

// ---------------------------------------------------------------------------
// msg via tensor cores: per (n,h,128-l-tile):
//   M[l, h*64+v] = S * (Q[l,:] @ KV[:,v]) / (Q[l,:] . Ksum + eps)
// ---------------------------------------------------------------------------
#define MROWB 144
__global__ void __launch_bounds__(128)
msg_tc_kernel()
{
    __shared__ __align__(16) uint8_t smQ[128 * MROWB];
    __shared__ __align__(16) uint8_t smB[64 * MROWB];   // KV fp16, rows=d cols=v
    __shared__ float Kss[HD];

    const int n = blockIdx.z, h = blockIdx.y, lt = blockIdx.x;
    const int tid  = threadIdx.x;
    const int wr   = tid >> 5;
    const int lane = tid & 31;

    const uint32_t sQ = smem_u32(smQ);
    const uint32_t sB = smem_u32(smB);

    const char* gQ = (const char*)g_Qh +
        ((size_t)(n * LL + lt * 128) * CC + h * HD) * 2;
    const float* gKV = g_KV + (size_t)(n * NH + h) * HD * HD;

#pragma unroll
    for (int i = 0; i < 8; i++) {
        const int slot = tid + i * 128;
        const int r = slot >> 3, c = (slot & 7) * 16;
        cpasync16(sQ + r * MROWB + c, gQ + (size_t)r * CC * 2 + c);
    }
    cp_commit();

#pragma unroll
    for (int i = 0; i < 32; i++) {
        const int idx = tid + i * 128;
        const int d = idx >> 6, v = idx & 63;
        *(__half*)(smB + d * MROWB + v * 2) = __float2half_rn(gKV[idx]);
    }
    if (tid < HD) Kss[tid] = g_Ks[(n * NH + h) * HD + tid];
    cp_wait<0>();
    __syncthreads();

    const uint32_t aRow = (uint32_t)(wr * 32 + (lane & 15));
    const uint32_t aCol = (uint32_t)((lane >> 4) << 4);
    const uint32_t bRow = (uint32_t)((((lane >> 3) & 1) << 3) + (lane & 7));
    const uint32_t bColB = (uint32_t)((lane >> 4) << 4);

    float acc[2][8][4];
#pragma unroll
    for (int i = 0; i < 2; i++)
#pragma unroll
        for (int j = 0; j < 8; j++)
#pragma unroll
            for (int q = 0; q < 4; q++) acc[i][j][q] = 0.f;

#pragma unroll
    for (int ks = 0; ks < 4; ks++) {
        const uint32_t kb = (uint32_t)(ks * 32);
        uint32_t a[2][4], b[4][4];
#pragma unroll
        for (int mi = 0; mi < 2; mi++)
            ldm_x4p(a[mi], sQ + (aRow + mi * 16) * MROWB + kb + aCol);
#pragma unroll
        for (int g = 0; g < 4; g++)
            ldm_x4_t(b[g], sB + (ks * 16 + bRow) * MROWB + bColB + g * 32);
#pragma unroll
        for (int mi = 0; mi < 2; mi++)
#pragma unroll
            for (int ni = 0; ni < 8; ni++)
                mma16816(acc[mi][ni], a[mi], &b[ni >> 1][(ni & 1) * 2]);
    }

#pragma unroll
    for (int mi = 0; mi < 2; mi++) {
        const int r0 = wr * 32 + mi * 16 + (lane >> 2);
        float zd0 = EPS_Z, zd1 = EPS_Z;
        const __half2* q0 = (const __half2*)(smQ + r0 * MROWB);
        const __half2* q1 = (const __half2*)(smQ + (r0 + 8) * MROWB);
#pragma unroll
        for (int k = 0; k < HD / 2; k++) {
            const float2 a0 = __half22float2(q0[k]);
            const float2 a1 = __half22float2(q1[k]);
            zd0 = fmaf(a0.x, Kss[2 * k], fmaf(a0.y, Kss[2 * k + 1], zd0));
            zd1 = fmaf(a1.x, Kss[2 * k], fmaf(a1.y, Kss[2 * k + 1], zd1));
        }
        const float zs0 = (float)SEQS / zd0;
        const float zs1 = (float)SEQS / zd1;

        const size_t base0 = ((size_t)(n * LL + lt * 128 + r0)) * CC + h * HD;
        const size_t base1 = base0 + (size_t)8 * CC;
#pragma unroll
        for (int ni = 0; ni < 8; ni++) {
            const int cn = ni * 8 + (lane & 3) * 2;
            *(__half2*)(g_Mh + base0 + cn) =
                __half2(__float2half_rn(acc[mi][ni][0] * zs0),
                        __float2half_rn(acc[mi][ni][1] * zs0));
            *(__half2*)(g_Mh + base1 + cn) =
                __half2(__float2half_rn(acc[mi][ni][2] * zs1),
                        __float2half_rn(acc[mi][ni][3] * zs1));
        }
    }
}

// ---------------------------------------------------------------------------
// Block reduction helper (256 threads)
// ---------------------------------------------------------------------------
__device__ __forceinline__ float block_reduce_sum(float v)
{
    __shared__ float red[8];
    const int lane = threadIdx.x & 31, w = threadIdx.x >> 5;
#pragma unroll
    for (int o = 16; o; o >>= 1) v += __shfl_down_sync(0xffffffffu, v, o);
    if (lane == 0) red[w] = v;
    __syncthreads();
    float t = (threadIdx.x < 8) ? red[threadIdx.x] : 0.f;
    if (w == 0) {
#pragma unroll
        for (int o = 4; o; o >>= 1) t += __shfl_down_sync(0xffu, t, o);
        if (lane == 0) red[0] = t;
    }
    __syncthreads();
    float r = red[0];
    __syncthreads();
    return r;
}

// ---------------------------------------------------------------------------
// LN(M1 fp16) -> fp16. Fully vectorized: 256 threads x one half2 (CC=512).
// ---------------------------------------------------------------------------
__global__ void __launch_bounds__(256)
ln_split_kernel(const float* __restrict__ g, const float* __restrict__ b)
{
    const int row = blockIdx.x;
    const int tid = threadIdx.x;

    const float2 mv = __half22float2(
        *(const __half2*)(g_M1h + (size_t)row * CC + tid * 2));

    const float mean = block_reduce_sum(mv.x + mv.y) * (1.f / CC);
    const float d0 = mv.x - mean, d1 = mv.y - mean;
    const float var = block_reduce_sum(d0 * d0 + d1 * d1) * (1.f / CC);
    const float rstd = rsqrtf(var + LN_EPS);

    const float2 gv = *(const float2*)(g + tid * 2);
    const float2 bv = *(const float2*)(b + tid * 2);
    *(__half2*)(g_mlnh + (size_t)row * CC + tid * 2) =
        __half2(__float2half_rn(d0 * rstd * gv.x + bv.x),
                __float2half_rn(d1 * rstd * gv.y + bv.y));
}

// ---------------------------------------------------------------------------
// out = x + LN(M2 fp16). Fully vectorized: 256 threads x one half2/float2.
// ---------------------------------------------------------------------------
__global__ void __launch_bounds__(256)
ln_add_kernel(const float* __restrict__ x,
              const float* __restrict__ g, const float* __restrict__ b,
              float* __restrict__ out)
{
    const int row = blockIdx.x;
    const int tid = threadIdx.x;

    const float2 mv = __half22float2(
        *(const __half2*)(g_M2h + (size_t)row * CC + tid * 2));

    const float mean = block_reduce_sum(mv.x + mv.y) * (1.f / CC);
    const float d0 = mv.x - mean, d1 = mv.y - mean;
    const float var = block_reduce_sum(d0 * d0 + d1 * d1) * (1.f / CC);
    const float rstd = rsqrtf(var + LN_EPS);

    const float2 gv = *(const float2*)(g + tid * 2);
    const float2 bv = *(const float2*)(b + tid * 2);
    const float2 xv = *(const float2*)(x + (size_t)row * CC + tid * 2);
    *(float2*)(out + (size_t)row * CC + tid * 2) =
        make_float2(xv.x + d0 * rstd * gv.x + bv.x,
                    xv.y + d1 * rstd * gv.y + bv.y);
}

// ---------------------------------------------------------------------------
// Launcher
// ---------------------------------------------------------------------------
extern "C" void kernel_launch(void* const* d_in, const int* in_sizes, int n_in,
                              void* d_out, int out_size)
{
    const float* x  = (const float*)d_in[0];
    const float* y  = (const float*)d_in[1];
    const float* Wq = (const float*)d_in[2];
    const float* Wk = (const float*)d_in[3];
    const float* Wv = (const float*)d_in[4];
    const float* Wm = (const float*)d_in[5];
    const float* W1 = (const float*)d_in[6];
    const float* W2 = (const float*)d_in[7];
    const float* g1 = (const float*)d_in[8];
    const float* b1 = (const float*)d_in[9];
    const float* g2 = (const float*)d_in[10];
    const float* b2 = (const float*)d_in[11];
    float* out = (float*)d_out;

    __half *qh,*kh,*vh,*xh,*yh,*wqh,*wkh,*wvh,*wmh,*w1h,*w2h;
    __half *mh,*m1h,*m2h,*mlnh,*h1h;
    cudaGetSymbolAddress((void**)&qh,  g_Qh);
    cudaGetSymbolAddress((void**)&kh,  g_Kh);
    cudaGetSymbolAddress((void**)&vh,  g_Vh);
    cudaGetSymbolAddress((void**)&xh,  g_xh);
    cudaGetSymbolAddress((void**)&yh,  g_yh);
    cudaGetSymbolAddress((void**)&wqh, g_Wqh);
    cudaGetSymbolAddress((void**)&wkh, g_Wkh);
    cudaGetSymbolAddress((void**)&wvh, g_Wvh);
    cudaGetSymbolAddress((void**)&wmh, g_Wmh);
    cudaGetSymbolAddress((void**)&w1h, g_W1h);
    cudaGetSymbolAddress((void**)&w2h, g_W2h);
    cudaGetSymbolAddress((void**)&mh,  g_Mh);
    cudaGetSymbolAddress((void**)&m1h, g_M1h);
    cudaGetSymbolAddress((void**)&m2h, g_M2h);
    cudaGetSymbolAddress((void**)&mlnh,g_mlnh);
    cudaGetSymbolAddress((void**)&h1h, g_H1h);

    cudaFuncSetAttribute(hmma_gemm<2>, cudaFuncAttributeMaxDynamicSharedMemorySize, SMEM_GEMM);
    cudaFuncSetAttribute(hmma_gemm<4>, cudaFuncAttributeMaxDynamicSharedMemorySize, SMEM_GEMM);
    cudaFuncSetAttribute(hmma_gemm<5>, cudaFuncAttributeMaxDynamicSharedMemorySize, SMEM_GEMM);

    // ---- one mega split launch
    SplitJobs J;
    const float* srcs[NSPLIT] = {x, y, Wq, Wk, Wv, Wm, W1, W2};
    __half* his[NSPLIT] = {xh, yh, wqh, wkh, wvh, wmh, w1h, w2h};
    const int n4s[NSPLIT] = {NTOK * CC / 4, NTOK * CC / 4, CC * CC / 4, CC * CC / 4,
                             CC * CC / 4, CC * CC / 4, C2 * C2 / 4, CC * C2 / 4};
    int off = 0;
    for (int j = 0; j < NSPLIT; j++) {
        J.src[j] = srcs[j]; J.hi[j] = his[j]; J.n4[j] = n4s[j];
        J.blkoff[j] = off;
        off += (n4s[j] + 255) / 256;
    }
    J.blkoff[NSPLIT] = off;
    split_all<<<off, 256>>>(J);

    const dim3 gQKV(3 * CC / 128, NTOK / 128);  // 12 x 128 (Q, K, V)
    const dim3 gP  (CC / 128, NTOK / 128);      // 4 x 128
    const dim3 gW1 (C2 / 128, NTOK / 128);      // 8 x 128
    const size_t sC = (size_t)CC * 2, sC2 = (size_t)C2 * 2;

    // merged Q,K,V projections
    hmma_gemm<4><<<gQKV, 256, SMEM_GEMM>>>(xh, yh, wqh, wkh, wvh,
                                           qh, kh, vh, CC, CC, 9999,
                                           sC, sC, 1.f / (float)SEQS);

    zero_kv_kernel<<<(NB * NH * HD * HD + 255) / 256, 256>>>();
    kv_kernel<<<dim3(KV_SPLIT, NH, NB), 256>>>();
    msg_tc_kernel<<<dim3(LL / 128, NH, NB), 128>>>();

    // Wm: fp16 message -> fp16 M1
    hmma_gemm<5><<<gP, 256, SMEM_GEMM>>>(mh, mh, wmh, nullptr, nullptr,
                                         m1h, nullptr, nullptr,
                                         CC, CC, 9999, sC, sC, 1.f);
    ln_split_kernel<<<NTOK, 256>>>(g1, b1);
    // W1: relu -> fp16; A = [x | LN(msg)] dual source (chunks 0-15 x, 16-31 mln)
    hmma_gemm<2><<<gW1, 256, SMEM_GEMM>>>(xh, mlnh, w1h, nullptr, nullptr,
                                          h1h, nullptr, nullptr,
                                          C2, C2, 16, sC, sC, 1.f);
    // W2 -> fp16 M2
    hmma_gemm<5><<<gP, 256, SMEM_GEMM>>>(h1h, h1h, w2h, nullptr, nullptr,
                                         m2h, nullptr, nullptr,
                                         CC, C2, 9999, sC2, sC2, 1.f);
    ln_add_kernel<<<NTOK, 256>>>(x, g2, b2, out);
}

// round 16
// speedup vs baseline: 1.1917x; 1.0088x over previous
#include <cuda_runtime.h>
#include <cuda_fp16.h>
#include <math.h>
#include <stdint.h>

// ---------------------------------------------------------------------------
// Problem constants
// ---------------------------------------------------------------------------
#define NB   4
#define LL   4096
#define SEQS 4096
#define CC   512
#define NH   8
#define HD   64
#define C2   1024
#define NTOK (NB * LL)          // 16384
#define EPS_Z 1e-6f
#define LN_EPS 1e-5f

// ---------------------------------------------------------------------------
// Scratch (device globals; no allocation allowed)
// ---------------------------------------------------------------------------
__device__ __align__(16) float g_KV[NB * NH * HD * HD];
__device__ __align__(16) float g_Ks[NB * NH * HD];

// fp16 buffers
__device__ __align__(16) __half g_Qh[(size_t)NTOK * CC];
__device__ __align__(16) __half g_Kh[(size_t)NTOK * CC];
__device__ __align__(16) __half g_Vh[(size_t)NTOK * CC];
__device__ __align__(16) __half g_xh[(size_t)NTOK * CC];
__device__ __align__(16) __half g_yh[(size_t)NTOK * CC];
__device__ __align__(16) __half g_Wqh[CC * CC];
__device__ __align__(16) __half g_Wkh[CC * CC];
__device__ __align__(16) __half g_Wvh[CC * CC];
__device__ __align__(16) __half g_Wmh[CC * CC];
__device__ __align__(16) __half g_W1h[C2 * C2];
__device__ __align__(16) __half g_W2h[CC * C2];
__device__ __align__(16) __half g_Mh  [(size_t)NTOK * CC];
__device__ __align__(16) __half g_M1h [(size_t)NTOK * CC];
__device__ __align__(16) __half g_M2h [(size_t)NTOK * CC];
__device__ __align__(16) __half g_mlnh[(size_t)NTOK * CC];
__device__ __align__(16) __half g_H1h [(size_t)NTOK * C2];

// ---------------------------------------------------------------------------
// PTX helpers
// ---------------------------------------------------------------------------
__device__ __forceinline__ uint32_t smem_u32(const void* p)
{
    uint32_t a;
    asm("{ .reg .u64 t; cvta.to.shared.u64 t, %1; cvt.u32.u64 %0, t; }"
        : "=r"(a) : "l"(p));
    return a;
}

__device__ __forceinline__ void cpasync16(uint32_t dst, const void* src)
{
    asm volatile("cp.async.cg.shared.global [%0], [%1], 16;"
                 :: "r"(dst), "l"(src) : "memory");
}
__device__ __forceinline__ void cp_commit()
{
    asm volatile("cp.async.commit_group;" ::: "memory");
}
template <int N>
__device__ __forceinline__ void cp_wait()
{
    asm volatile("cp.async.wait_group %0;" :: "n"(N) : "memory");
}

__device__ __forceinline__ void ldm_x4(uint32_t& r0, uint32_t& r1,
                                       uint32_t& r2, uint32_t& r3, uint32_t a)
{
    asm volatile("ldmatrix.sync.aligned.m8n8.x4.shared.b16 {%0,%1,%2,%3}, [%4];"
                 : "=r"(r0), "=r"(r1), "=r"(r2), "=r"(r3) : "r"(a));
}

__device__ __forceinline__ void ldm_x4p(uint32_t* r, uint32_t a)
{
    asm volatile("ldmatrix.sync.aligned.m8n8.x4.shared.b16 {%0,%1,%2,%3}, [%4];"
                 : "=r"(r[0]), "=r"(r[1]), "=r"(r[2]), "=r"(r[3]) : "r"(a));
}

__device__ __forceinline__ void ldm_x4_t(uint32_t* r, uint32_t a)
{
    asm volatile("ldmatrix.sync.aligned.m8n8.x4.trans.shared.b16 {%0,%1,%2,%3}, [%4];"
                 : "=r"(r[0]), "=r"(r[1]), "=r"(r[2]), "=r"(r[3]) : "r"(a));
}

__device__ __forceinline__ void mma16816(float* c, const uint32_t* a,
                                         const uint32_t* b)
{
    asm volatile(
        "mma.sync.aligned.m16n8k16.row.col.f32.f16.f16.f32 "
        "{%0,%1,%2,%3}, {%4,%5,%6,%7}, {%8,%9}, {%0,%1,%2,%3};"
        : "+f"(c[0]), "+f"(c[1]), "+f"(c[2]), "+f"(c[3])
        : "r"(a[0]), "r"(a[1]), "r"(a[2]), "r"(a[3]), "r"(b[0]), "r"(b[1]));
}

// ---------------------------------------------------------------------------
// Mega split: fp32 -> fp16 (2x float4 per thread) + zero job for KV/Ksum
// ---------------------------------------------------------------------------
#define NSPLIT 8
struct SplitJobs {
    const float* src[NSPLIT];
    __half* hi[NSPLIT];
    int n4[NSPLIT];
    int blkoff[NSPLIT + 2];      // last range = zero job
    float* kvp;
    float* ksp;
};

__global__ void __launch_bounds__(256)
split_all(SplitJobs J)
{
    int b = blockIdx.x;
    if (b >= J.blkoff[NSPLIT]) {                     // zero job
        const int i = (b - J.blkoff[NSPLIT]) * 256 + threadIdx.x;
        if (i < NB * NH * HD * HD) J.kvp[i] = 0.f;
        if (i < NB * NH * HD)      J.ksp[i] = 0.f;
        return;
    }
    int j = 0;
#pragma unroll
    for (int t = 0; t < NSPLIT - 1; t++)
        if (b >= J.blkoff[t + 1]) j = t + 1;
    const int base = (b - J.blkoff[j]) * 512 + threadIdx.x;
#pragma unroll
    for (int u = 0; u < 2; u++) {
        const int i = base + u * 256;
        if (i >= J.n4[j]) break;
        float4 v = ((const float4*)J.src[j])[i];
        ((__half2*)J.hi[j])[i * 2 + 0] =
            __half2(__float2half_rn(v.x), __float2half_rn(v.y));
        ((__half2*)J.hi[j])[i * 2 + 1] =
            __half2(__float2half_rn(v.z), __float2half_rn(v.w));
    }
}

// ---------------------------------------------------------------------------
// fp16 1-pass HMMA GEMM. Tile 128x128, BK=32 fp32-K, 4-stage cp.async,
// 8 warps 2x4, dual A-source (kSplit). EPI:
//   2 = relu -> fp16 Ch
//   4 = merged QKV: seg=bx>>2: 0 -> elu(A1@Bh)->Ch, 1 -> elu(A2@B2h)->Ch2,
//                   2 -> (A2@B3h)*scale -> Ch3
//   5 = *scale -> fp16 Ch
// ---------------------------------------------------------------------------
#define ROWB   80
#define MATB   (128 * ROWB)       // 10240 B
#define STAGEB (2 * MATB)         // 20480 B (Ah, Bh)
#define NSTG   4
#define SMEM_GEMM (NSTG * STAGEB) // 81920 B

template <int EPI>
__global__ void __launch_bounds__(256, 2)
hmma_gemm(const __half* __restrict__ A1h, const __half* __restrict__ A2h,
          const __half* __restrict__ Bh, const __half* __restrict__ B2h,
          const __half* __restrict__ B3h,
          __half* __restrict__ Ch, __half* __restrict__ Ch2,
          __half* __restrict__ Ch3,
          int N, int K, int kSplit,
          size_t sA1b, size_t sA2b, float scale)
{
    extern __shared__ __align__(16) uint8_t dynsm[];
    const uint32_t sbase = smem_u32(dynsm);

    const int tid  = threadIdx.x;
    const int wid  = tid >> 5;
    const int lane = tid & 31;
    const int wr   = wid >> 2;
    const int wc   = wid & 3;
    const int bx   = blockIdx.x;
    const int by   = blockIdx.y;

    const int seg = (EPI == 4) ? (bx >> 2) : 0;
    const int bn  = (EPI == 4) ? (bx & 3) : bx;
    const __half* Bsel = Bh;
    if (EPI == 4) Bsel = (seg == 0) ? Bh : ((seg == 1) ? B2h : B3h);
    const int kS = (EPI == 4) ? ((seg == 0) ? 9999 : 0) : kSplit;

    const int row0 = tid >> 2;               // 0..63
    const int cb   = (tid & 3) * 16;
    const size_t sBb = (size_t)K * 2;

    const char* gA1h = (const char*)A1h + (size_t)(by * 128 + row0) * sA1b + cb;
    const char* gA2h = (const char*)A2h + (size_t)(by * 128 + row0) * sA2b + cb;
    const char* gBh0 = (const char*)Bsel + (size_t)(bn * 128 + row0) * sBb + cb;
    const size_t rs1 = 64 * sA1b, rs2 = 64 * sA2b, rsB = 64 * sBb;

    const uint32_t dA0 = (uint32_t)(row0 * ROWB + cb);
    const uint32_t dA1 = (uint32_t)((row0 + 64) * ROWB + cb);

    auto issue = [&](int stage, int chunk) {
        const uint32_t s = sbase + stage * STAGEB;
        const char *ah; size_t o, rs;
        if (chunk < kS) { ah = gA1h; o = (size_t)chunk * 64; rs = rs1; }
        else { ah = gA2h; o = (size_t)(chunk - kS) * 64; rs = rs2; }
        cpasync16(s + dA0, ah + o);
        cpasync16(s + dA1, ah + o + rs);
        const size_t ob = (size_t)chunk * 64;
        cpasync16(s + MATB + dA0, gBh0 + ob);
        cpasync16(s + MATB + dA1, gBh0 + ob + rsB);
        cp_commit();
    };

    const uint32_t aRow = (uint32_t)(wr * 64 + (lane & 15));
    const uint32_t aCol = (uint32_t)((lane >> 4) << 4);
    const uint32_t bRow = (uint32_t)(wc * 32 + (lane & 7) + ((lane >> 4) << 3));
    const uint32_t bCol = (uint32_t)(((lane >> 3) & 1) << 4);

    float acc[4][4][4];
#pragma unroll
    for (int i = 0; i < 4; i++)
#pragma unroll
        for (int j = 0; j < 4; j++)
#pragma unroll
            for (int q = 0; q < 4; q++) acc[i][j][q] = 0.f;

    const int nch = K / 32;
    issue(0, 0);
    if (nch > 1) issue(1, 1);

    for (int c = 0; c < nch; c++) {
        if (c + 2 < nch) { issue((c + 2) % NSTG, c + 2); cp_wait<2>(); }
        else if (c + 1 < nch) { cp_wait<1>(); }
        else { cp_wait<0>(); }
        __syncthreads();

        const uint32_t s  = sbase + (c % NSTG) * STAGEB;
        const uint32_t pAh = s, pBh = s + MATB;

#pragma unroll
        for (int ks = 0; ks < 2; ks++) {
            const uint32_t kb = (uint32_t)(ks * 32);

            uint32_t ah[4][4], bh[2][4];
#pragma unroll
            for (int mi = 0; mi < 4; mi++)
                ldm_x4(ah[mi][0], ah[mi][1], ah[mi][2], ah[mi][3],
                       pAh + (aRow + mi * 16) * ROWB + kb + aCol);
#pragma unroll
            for (int ng = 0; ng < 2; ng++)
                ldm_x4(bh[ng][0], bh[ng][1], bh[ng][2], bh[ng][3],
                       pBh + (bRow + ng * 16) * ROWB + kb + bCol);
#pragma unroll
            for (int mi = 0; mi < 4; mi++)
#pragma unroll
                for (int ni = 0; ni < 4; ni++)
                    mma16816(acc[mi][ni], ah[mi], &bh[ni >> 1][(ni & 1) * 2]);
        }
        __syncthreads();
    }

    // ---- epilogue
#pragma unroll
    for (int mi = 0; mi < 4; mi++) {
#pragma unroll
        for (int ni = 0; ni < 4; ni++) {
            const int r = by * 128 + wr * 64 + mi * 16 + (lane >> 2);
            const int cn = bn * 128 + wc * 32 + ni * 8 + (lane & 3) * 2;
            float v0 = acc[mi][ni][0];
            float v1 = acc[mi][ni][1];
            float v2 = acc[mi][ni][2];
            float v3 = acc[mi][ni][3];
            if (EPI == 5 || (EPI == 4 && seg == 2)) {
                v0 *= scale; v1 *= scale; v2 *= scale; v3 *= scale;
            }
            if (EPI == 4 && seg < 2) {
                v0 = (v0 > 0.f) ? (v0 + 1.f) : expf(v0);
                v1 = (v1 > 0.f) ? (v1 + 1.f) : expf(v1);
                v2 = (v2 > 0.f) ? (v2 + 1.f) : expf(v2);
                v3 = (v3 > 0.f) ? (v3 + 1.f) : expf(v3);
            }
            if (EPI == 2) {
                v0 = fmaxf(v0, 0.f); v1 = fmaxf(v1, 0.f);
                v2 = fmaxf(v2, 0.f); v3 = fmaxf(v3, 0.f);
            }

            __half* outp = Ch;
            if (EPI == 4) outp = (seg == 0) ? Ch : ((seg == 1) ? Ch2 : Ch3);
            *(__half2*)(outp + (size_t)r * N + cn) =
                __half2(__float2half_rn(v0), __float2half_rn(v1));
            *(__half2*)(outp + (size_t)(r + 8) * N + cn) =
                __half2(__float2half_rn(v2), __float2half_rn(v3));
        }
    }
}

// ---------------------------------------------------------------------------
// KV via tensor cores: KV[n,h] = K^T @ V (+ Ksum) over this block's s-range.
// Ksum spread over all 256 threads (tid&63 = d, tid>>6 = s-quarter of 16).
// ---------------------------------------------------------------------------
#define KV_SPLIT 16
#define KROWB  144
#define KTILEB (64 * KROWB)

__global__ void __launch_bounds__(256)
kv_kernel()
{
    __shared__ __align__(16) uint8_t sm[4 * KTILEB];   // K0,V0,K1,V1
    const uint32_t sbase = smem_u32(sm);

    const int n = blockIdx.z, h = blockIdx.y, sp = blockIdx.x;
    const int s0 = sp * (SEQS / KV_SPLIT);
    const int tid  = threadIdx.x;
    const int wid  = tid >> 5;
    const int lane = tid & 31;
    const int d0   = (wid & 3) * 16;
    const int v0   = (wid >> 2) * 32;

    const char* gK = (const char*)g_Kh + ((size_t)(n * SEQS + s0) * CC + h * HD) * 2;
    const char* gV = (const char*)g_Vh + ((size_t)(n * SEQS + s0) * CC + h * HD) * 2;

    auto issue = [&](int stage, int chunk) {
        const uint32_t sK = sbase + stage * 2 * KTILEB;
        const uint32_t sV = sK + KTILEB;
        const size_t goff = (size_t)chunk * 64 * CC * 2;
#pragma unroll
        for (int i = 0; i < 2; i++) {
            const int slot = tid + i * 256;
            const int r  = slot >> 3;
            const int cc = (slot & 7) * 16;
            cpasync16(sK + r * KROWB + cc, gK + goff + (size_t)r * CC * 2 + cc);
            cpasync16(sV + r * KROWB + cc, gV + goff + (size_t)r * CC * 2 + cc);
        }
        cp_commit();
    };

    const uint32_t aRow = (uint32_t)(((lane >> 4) << 3) + (lane & 7));
    const uint32_t aCol = (uint32_t)((d0 + ((lane >> 3) & 1) * 8) * 2);
    const uint32_t bRow = (uint32_t)((((lane >> 3) & 1) << 3) + (lane & 7));
    const uint32_t bColBase = (uint32_t)((v0 + (lane >> 4) * 8) * 2);

    float acc[4][4];
#pragma unroll
    for (int i = 0; i < 4; i++)
#pragma unroll
        for (int q = 0; q < 4; q++) acc[i][q] = 0.f;
    float ksacc = 0.f;

    // Ksum geometry: all 256 threads, each 16 rows of one d-column
    const int ksd = tid & 63;
    const int ksr = (tid >> 6) * 16;

    issue(0, 0);
    const int nch = (SEQS / KV_SPLIT) / 64;

    for (int c = 0; c < nch; c++) {
        cp_wait<0>();
        __syncthreads();
        if (c + 1 < nch) issue((c + 1) & 1, c + 1);

        const uint32_t sK = sbase + (c & 1) * 2 * KTILEB;
        const uint32_t sV = sK + KTILEB;

#pragma unroll
        for (int ks = 0; ks < 4; ks++) {
            const uint32_t srow = (uint32_t)(ks * 16);
            uint32_t a[4], b0[4], b1[4];
            ldm_x4_t(a,  sK + (srow + aRow) * KROWB + aCol);
            ldm_x4_t(b0, sV + (srow + bRow) * KROWB + bColBase);
            ldm_x4_t(b1, sV + (srow + bRow) * KROWB + bColBase + 32);
            mma16816(acc[0], a, &b0[0]);
            mma16816(acc[1], a, &b0[2]);
            mma16816(acc[2], a, &b1[0]);
            mma16816(acc[3], a, &b1[2]);
        }

        {
            const uint32_t boff = (c & 1) * 2 * KTILEB +
                                  (uint32_t)(ksd * 2) + (uint32_t)(ksr * KROWB);
#pragma unroll
            for (int s = 0; s < 16; s++)
                ksacc += __half2float(*(const __half*)(sm + boff + s * KROWB));
        }
        __syncthreads();
    }

    float* KVp = g_KV + (size_t)(n * NH + h) * HD * HD;
    const int dr = d0 + (lane >> 2);
    const int vc = (lane & 3) * 2;
#pragma unroll
    for (int ni = 0; ni < 4; ni++) {
        const int v = v0 + ni * 8 + vc;
        atomicAdd(&KVp[(size_t)dr * HD + v],           acc[ni][0]);
        atomicAdd(&KVp[(size_t)dr * HD + v + 1],       acc[ni][1]);
        atomicAdd(&KVp[(size_t)(dr + 8) * HD + v],     acc[ni][2]);
        atomicAdd(&KVp[(size_t)(dr + 8) * HD + v + 1], acc[ni][3]);
    }
    atomicAdd(&g_Ks[(n * NH + h) * HD + ksd], ksacc);
}

// ---------------------------------------------------------------------------
// msg via tensor cores: per (n,h,128-l-tile):
//   M[l, h*64+v] = S * (Q[l,:] @ KV[:,v]) / (Q[l,:] . Ksum + eps)
// ---------------------------------------------------------------------------
#define MROWB 144
__global__ void __launch_bounds__(128)
msg_tc_kernel()
{
    __shared__ __align__(16) uint8_t smQ[128 * MROWB];
    __shared__ __align__(16) uint8_t smB[64 * MROWB];   // KV fp16, rows=d cols=v
    __shared__ float Kss[HD];

    const int n = blockIdx.z, h = blockIdx.y, lt = blockIdx.x;
    const int tid  = threadIdx.x;
    const int wr   = tid >> 5;
    const int lane = tid & 31;

    const uint32_t sQ = smem_u32(smQ);
    const uint32_t sB = smem_u32(smB);

    const char* gQ = (const char*)g_Qh +
        ((size_t)(n * LL + lt * 128) * CC + h * HD) * 2;
    const float* gKV = g_KV + (size_t)(n * NH + h) * HD * HD;

#pragma unroll
    for (int i = 0; i < 8; i++) {
        const int slot = tid + i * 128;
        const int r = slot >> 3, c = (slot & 7) * 16;
        cpasync16(sQ + r * MROWB + c, gQ + (size_t)r * CC * 2 + c);
    }
    cp_commit();

#pragma unroll
    for (int i = 0; i < 32; i++) {
        const int idx = tid + i * 128;
        const int d = idx >> 6, v = idx & 63;
        *(__half*)(smB + d * MROWB + v * 2) = __float2half_rn(gKV[idx]);
    }
    if (tid < HD) Kss[tid] = g_Ks[(n * NH + h) * HD + tid];
    cp_wait<0>();
    __syncthreads();

    const uint32_t aRow = (uint32_t)(wr * 32 + (lane & 15));
    const uint32_t aCol = (uint32_t)((lane >> 4) << 4);
    const uint32_t bRow = (uint32_t)((((lane >> 3) & 1) << 3) + (lane & 7));
    const uint32_t bColB = (uint32_t)((lane >> 4) << 4);

    float acc[2][8][4];
#pragma unroll
    for (int i = 0; i < 2; i++)
#pragma unroll
        for (int j = 0; j < 8; j++)
#pragma unroll
            for (int q = 0; q < 4; q++) acc[i][j][q] = 0.f;

#pragma unroll
    for (int ks = 0; ks < 4; ks++) {
        const uint32_t kb = (uint32_t)(ks * 32);
        uint32_t a[2][4], b[4][4];
#pragma unroll
        for (int mi = 0; mi < 2; mi++)
            ldm_x4p(a[mi], sQ + (aRow + mi * 16) * MROWB + kb + aCol);
#pragma unroll
        for (int g = 0; g < 4; g++)
            ldm_x4_t(b[g], sB + (ks * 16 + bRow) * MROWB + bColB + g * 32);
#pragma unroll
        for (int mi = 0; mi < 2; mi++)
#pragma unroll
            for (int ni = 0; ni < 8; ni++)
                mma16816(acc[mi][ni], a[mi], &b[ni >> 1][(ni & 1) * 2]);
    }

#pragma unroll
    for (int mi = 0; mi < 2; mi++) {
        const int r0 = wr * 32 + mi * 16 + (lane >> 2);
        float zd0 = EPS_Z, zd1 = EPS_Z;
        const __half2* q0 = (const __half2*)(smQ + r0 * MROWB);
        const __half2* q1 = (const __half2*)(smQ + (r0 + 8) * MROWB);
#pragma unroll
        for (int k = 0; k < HD / 2; k++) {
            const float2 a0 = __half22float2(q0[k]);
            const float2 a1 = __half22float2(q1[k]);
            zd0 = fmaf(a0.x, Kss[2 * k], fmaf(a0.y, Kss[2 * k + 1], zd0));
            zd1 = fmaf(a1.x, Kss[2 * k], fmaf(a1.y, Kss[2 * k + 1], zd1));
        }
        const float zs0 = (float)SEQS / zd0;
        const float zs1 = (float)SEQS / zd1;

        const size_t base0 = ((size_t)(n * LL + lt * 128 + r0)) * CC + h * HD;
        const size_t base1 = base0 + (size_t)8 * CC;
#pragma unroll
        for (int ni = 0; ni < 8; ni++) {
            const int cn = ni * 8 + (lane & 3) * 2;
            *(__half2*)(g_Mh + base0 + cn) =
                __half2(__float2half_rn(acc[mi][ni][0] * zs0),
                        __float2half_rn(acc[mi][ni][1] * zs0));
            *(__half2*)(g_Mh + base1 + cn) =
                __half2(__float2half_rn(acc[mi][ni][2] * zs1),
                        __float2half_rn(acc[mi][ni][3] * zs1));
        }
    }
}

// ---------------------------------------------------------------------------
// Block reduction helper (256 threads)
// ---------------------------------------------------------------------------
__device__ __forceinline__ float block_reduce_sum(float v)
{
    __shared__ float red[8];
    const int lane = threadIdx.x & 31, w = threadIdx.x >> 5;
#pragma unroll
    for (int o = 16; o; o >>= 1) v += __shfl_down_sync(0xffffffffu, v, o);
    if (lane == 0) red[w] = v;
    __syncthreads();
    float t = (threadIdx.x < 8) ? red[threadIdx.x] : 0.f;
    if (w == 0) {
#pragma unroll
        for (int o = 4; o; o >>= 1) t += __shfl_down_sync(0xffu, t, o);
        if (lane == 0) red[0] = t;
    }
    __syncthreads();
    float r = red[0];
    __syncthreads();
    return r;
}

// ---------------------------------------------------------------------------
// LN(M1 fp16) -> fp16. Fully vectorized: 256 threads x one half2 (CC=512).
// ---------------------------------------------------------------------------
__global__ void __launch_bounds__(256)
ln_split_kernel(const float* __restrict__ g, const float* __restrict__ b)
{
    const int row = blockIdx.x;
    const int tid = threadIdx.x;

    const float2 mv = __half22float2(
        *(const __half2*)(g_M1h + (size_t)row * CC + tid * 2));

    const float mean = block_reduce_sum(mv.x + mv.y) * (1.f / CC);
    const float d0 = mv.x - mean, d1 = mv.y - mean;
    const float var = block_reduce_sum(d0 * d0 + d1 * d1) * (1.f / CC);
    const float rstd = rsqrtf(var + LN_EPS);

    const float2 gv = *(const float2*)(g + tid * 2);
    const float2 bv = *(const float2*)(b + tid * 2);
    *(__half2*)(g_mlnh + (size_t)row * CC + tid * 2) =
        __half2(__float2half_rn(d0 * rstd * gv.x + bv.x),
                __float2half_rn(d1 * rstd * gv.y + bv.y));
}

// ---------------------------------------------------------------------------
// out = x + LN(M2 fp16). Fully vectorized: 256 threads x one half2/float2.
// ---------------------------------------------------------------------------
__global__ void __launch_bounds__(256)
ln_add_kernel(const float* __restrict__ x,
              const float* __restrict__ g, const float* __restrict__ b,
              float* __restrict__ out)
{
    const int row = blockIdx.x;
    const int tid = threadIdx.x;

    const float2 mv = __half22float2(
        *(const __half2*)(g_M2h + (size_t)row * CC + tid * 2));

    const float mean = block_reduce_sum(mv.x + mv.y) * (1.f / CC);
    const float d0 = mv.x - mean, d1 = mv.y - mean;
    const float var = block_reduce_sum(d0 * d0 + d1 * d1) * (1.f / CC);
    const float rstd = rsqrtf(var + LN_EPS);

    const float2 gv = *(const float2*)(g + tid * 2);
    const float2 bv = *(const float2*)(b + tid * 2);
    const float2 xv = *(const float2*)(x + (size_t)row * CC + tid * 2);
    *(float2*)(out + (size_t)row * CC + tid * 2) =
        make_float2(xv.x + d0 * rstd * gv.x + bv.x,
                    xv.y + d1 * rstd * gv.y + bv.y);
}

// ---------------------------------------------------------------------------
// Launcher
// ---------------------------------------------------------------------------
extern "C" void kernel_launch(void* const* d_in, const int* in_sizes, int n_in,
                              void* d_out, int out_size)
{
    const float* x  = (const float*)d_in[0];
    const float* y  = (const float*)d_in[1];
    const float* Wq = (const float*)d_in[2];
    const float* Wk = (const float*)d_in[3];
    const float* Wv = (const float*)d_in[4];
    const float* Wm = (const float*)d_in[5];
    const float* W1 = (const float*)d_in[6];
    const float* W2 = (const float*)d_in[7];
    const float* g1 = (const float*)d_in[8];
    const float* b1 = (const float*)d_in[9];
    const float* g2 = (const float*)d_in[10];
    const float* b2 = (const float*)d_in[11];
    float* out = (float*)d_out;

    float *kvp, *ksp;
    cudaGetSymbolAddress((void**)&kvp, g_KV);
    cudaGetSymbolAddress((void**)&ksp, g_Ks);

    __half *qh,*kh,*vh,*xh,*yh,*wqh,*wkh,*wvh,*wmh,*w1h,*w2h;
    __half *mh,*m1h,*m2h,*mlnh,*h1h;
    cudaGetSymbolAddress((void**)&qh,  g_Qh);
    cudaGetSymbolAddress((void**)&kh,  g_Kh);
    cudaGetSymbolAddress((void**)&vh,  g_Vh);
    cudaGetSymbolAddress((void**)&xh,  g_xh);
    cudaGetSymbolAddress((void**)&yh,  g_yh);
    cudaGetSymbolAddress((void**)&wqh, g_Wqh);
    cudaGetSymbolAddress((void**)&wkh, g_Wkh);
    cudaGetSymbolAddress((void**)&wvh, g_Wvh);
    cudaGetSymbolAddress((void**)&wmh, g_Wmh);
    cudaGetSymbolAddress((void**)&w1h, g_W1h);
    cudaGetSymbolAddress((void**)&w2h, g_W2h);
    cudaGetSymbolAddress((void**)&mh,  g_Mh);
    cudaGetSymbolAddress((void**)&m1h, g_M1h);
    cudaGetSymbolAddress((void**)&m2h, g_M2h);
    cudaGetSymbolAddress((void**)&mlnh,g_mlnh);
    cudaGetSymbolAddress((void**)&h1h, g_H1h);

    cudaFuncSetAttribute(hmma_gemm<2>, cudaFuncAttributeMaxDynamicSharedMemorySize, SMEM_GEMM);
    cudaFuncSetAttribute(hmma_gemm<4>, cudaFuncAttributeMaxDynamicSharedMemorySize, SMEM_GEMM);
    cudaFuncSetAttribute(hmma_gemm<5>, cudaFuncAttributeMaxDynamicSharedMemorySize, SMEM_GEMM);

    // ---- one mega split launch (+ zero job appended)
    SplitJobs J;
    const float* srcs[NSPLIT] = {x, y, Wq, Wk, Wv, Wm, W1, W2};
    __half* his[NSPLIT] = {xh, yh, wqh, wkh, wvh, wmh, w1h, w2h};
    const int n4s[NSPLIT] = {NTOK * CC / 4, NTOK * CC / 4, CC * CC / 4, CC * CC / 4,
                             CC * CC / 4, CC * CC / 4, C2 * C2 / 4, CC * C2 / 4};
    int off = 0;
    for (int j = 0; j < NSPLIT; j++) {
        J.src[j] = srcs[j]; J.hi[j] = his[j]; J.n4[j] = n4s[j];
        J.blkoff[j] = off;
        off += (n4s[j] + 511) / 512;
    }
    J.blkoff[NSPLIT] = off;
    off += (NB * NH * HD * HD + 255) / 256;    // zero job blocks
    J.blkoff[NSPLIT + 1] = off;
    J.kvp = kvp; J.ksp = ksp;
    split_all<<<off, 256>>>(J);

    const dim3 gQKV(3 * CC / 128, NTOK / 128);  // 12 x 128 (Q, K, V)
    const dim3 gP  (CC / 128, NTOK / 128);      // 4 x 128
    const dim3 gW1 (C2 / 128, NTOK / 128);      // 8 x 128
    const size_t sC = (size_t)CC * 2, sC2 = (size_t)C2 * 2;

    // merged Q,K,V projections
    hmma_gemm<4><<<gQKV, 256, SMEM_GEMM>>>(xh, yh, wqh, wkh, wvh,
                                           qh, kh, vh, CC, CC, 9999,
                                           sC, sC, 1.f / (float)SEQS);

    kv_kernel<<<dim3(KV_SPLIT, NH, NB), 256>>>();
    msg_tc_kernel<<<dim3(LL / 128, NH, NB), 128>>>();

    // Wm: fp16 message -> fp16 M1
    hmma_gemm<5><<<gP, 256, SMEM_GEMM>>>(mh, mh, wmh, nullptr, nullptr,
                                         m1h, nullptr, nullptr,
                                         CC, CC, 9999, sC, sC, 1.f);
    ln_split_kernel<<<NTOK, 256>>>(g1, b1);
    // W1: relu -> fp16; A = [x | LN(msg)] dual source (chunks 0-15 x, 16-31 mln)
    hmma_gemm<2><<<gW1, 256, SMEM_GEMM>>>(xh, mlnh, w1h, nullptr, nullptr,
                                          h1h, nullptr, nullptr,
                                          C2, C2, 16, sC, sC, 1.f);
    // W2 -> fp16 M2
    hmma_gemm<5><<<gP, 256, SMEM_GEMM>>>(h1h, h1h, w2h, nullptr, nullptr,
                                         m2h, nullptr, nullptr,
                                         CC, C2, 9999, sC2, sC2, 1.f);
    ln_add_kernel<<<NTOK, 256>>>(x, g2, b2, out);
}